// round 2
// baseline (speedup 1.0000x reference)
#include <cuda_runtime.h>

#define B        64
#define NV       100000
#define NE       (3 * NV)        // 300000 floats per batch row
#define NT       200000          // tets
#define NIDX     (3 * NT)        // 600000 indices
#define VOL_BLOCKS 1184

// Scratch (static device globals — no runtime allocation)
__device__ float g_xt[B * NE];              // transposed: xt[e*64 + b]
__device__ int   g_off[NIDX];               // precomputed offsets: idx*192
__device__ float g_part[VOL_BLOCKS * B];    // per-block partial |det| sums
__device__ float g_inv[B];                  // 1/cbrt(vol)
__device__ int   g_is64;                    // dtype probe result

// ---------------------------------------------------------------------------
// Kernel A: probe whether M is int64 (odd int32 words all zero) or int32.
// Deterministic pure function of the input buffer.
// ---------------------------------------------------------------------------
__global__ void k_detect(const int* __restrict__ Mi) {
    int nz = 0;
    #pragma unroll
    for (int k = 0; k < 32; k++) nz |= Mi[2 * k + 1];
    g_is64 = (nz == 0) ? 1 : 0;
}

// ---------------------------------------------------------------------------
// Kernel 0: indices -> int32 element offsets (idx * 192)
// ---------------------------------------------------------------------------
__global__ void k_prep(const void* __restrict__ Mv) {
    int t = blockIdx.x * blockDim.x + threadIdx.x;
    if (t >= NIDX) return;
    int idx;
    if (g_is64) idx = (int)((const long long*)Mv)[t];
    else        idx = ((const int*)Mv)[t];
    g_off[t] = idx * (3 * B);
}

// ---------------------------------------------------------------------------
// Kernel 1: transpose x[b][e] -> xt[e][b], tiles of 32 elements x 64 batches
// ---------------------------------------------------------------------------
__global__ void k_transpose(const float* __restrict__ x) {
    __shared__ float tile[32][65];
    const int e0 = blockIdx.x * 32;           // 300000/32 = 9375 blocks exact
    const int tid = threadIdx.x;              // 256 threads

    #pragma unroll
    for (int k = 0; k < 8; k++) {
        int b = (tid >> 5) + k * 8;           // 0..63
        int e = tid & 31;
        tile[e][b] = x[b * NE + e0 + e];
    }
    __syncthreads();
    #pragma unroll
    for (int k = 0; k < 8; k++) {
        int b = tid & 63;
        int e = (tid >> 6) + k * 4;           // 0..31
        g_xt[(e0 + e) * B + b] = tile[e][b];
    }
}

// ---------------------------------------------------------------------------
// Kernel 2: per-batch |det| partial sums.
// Block = 256 threads = 64 batches (lane-major) x 4 tet-streams.
// Lanes = 32 consecutive batches -> every xt load is one full 128B line.
// Index loads are warp-uniform. Deterministic: fixed partial per block.
// ---------------------------------------------------------------------------
__global__ void k_volume() {
    const int tid = threadIdx.x;
    const int b   = tid & 63;                 // batch
    const int sub = tid >> 6;                 // tet stream 0..3

    float acc = 0.0f;
    const int stride = VOL_BLOCKS * 4;
    for (int t = blockIdx.x * 4 + sub; t < NT; t += stride) {
        const int o0 = __ldg(&g_off[3 * t + 0]);
        const int o1 = __ldg(&g_off[3 * t + 1]);
        const int o2 = __ldg(&g_off[3 * t + 2]);

        const float* p0 = g_xt + o0 + b;
        const float* p1 = g_xt + o1 + b;
        const float* p2 = g_xt + o2 + b;

        float ax = p0[0], ay = p0[64], az = p0[128];
        float bx = p1[0], by = p1[64], bz = p1[128];
        float cx = p2[0], cy = p2[64], cz = p2[128];

        float det = ax * (by * cz - bz * cy)
                  - ay * (bx * cz - bz * cx)
                  + az * (bx * cy - by * cx);
        acc += fabsf(det);
    }

    __shared__ float sred[4][64];
    sred[sub][b] = acc;
    __syncthreads();
    if (sub == 0)
        g_part[blockIdx.x * B + b] =
            sred[0][b] + sred[1][b] + sred[2][b] + sred[3][b];
}

// ---------------------------------------------------------------------------
// Kernel 3: deterministic reduce of partials + inverse cube root.
// 256 threads: 64 batches x 4 streams over 1184 partial rows.
// ---------------------------------------------------------------------------
__global__ void k_reduce() {
    const int tid = threadIdx.x;
    const int b   = tid & 63;
    const int sub = tid >> 6;

    float s = 0.0f;
    for (int r = sub; r < VOL_BLOCKS; r += 4)
        s += g_part[r * B + b];

    __shared__ float sred[4][64];
    sred[sub][b] = s;
    __syncthreads();
    if (sub == 0) {
        float vol = (sred[0][b] + sred[1][b] + sred[2][b] + sred[3][b])
                    * (1.0f / 6.0f);
        g_inv[b] = 1.0f / cbrtf(vol);
    }
}

// ---------------------------------------------------------------------------
// Kernel 4: out = x * inv_scale[b], float4 streaming
// ---------------------------------------------------------------------------
__global__ void k_scale(const float* __restrict__ x, float* __restrict__ out) {
    const int bb = blockIdx.y;
    const int j4 = blockIdx.x * blockDim.x + threadIdx.x;
    const int n4 = NE / 4;                    // 75000
    if (j4 < n4) {
        float s = __ldg(&g_inv[bb]);
        const float4* xi = (const float4*)(x + bb * NE);
        float4*       oo = (float4*)(out + bb * NE);
        float4 v = xi[j4];
        v.x *= s; v.y *= s; v.z *= s; v.w *= s;
        oo[j4] = v;
    }
}

// ---------------------------------------------------------------------------
extern "C" void kernel_launch(void* const* d_in, const int* in_sizes, int n_in,
                              void* d_out, int out_size) {
    const float* x = (const float*)d_in[0];
    const void*  M = d_in[1];
    float*     out = (float*)d_out;

    k_detect<<<1, 1>>>((const int*)M);
    k_prep<<<(NIDX + 255) / 256, 256>>>(M);
    k_transpose<<<NE / 32, 256>>>(x);
    k_volume<<<VOL_BLOCKS, 256>>>();
    k_reduce<<<1, 256>>>();
    dim3 g((NE / 4 + 255) / 256, B);
    k_scale<<<g, 256>>>(x, out);
}

// round 3
// speedup vs baseline: 1.2769x; 1.2769x over previous
#include <cuda_runtime.h>

#define B        64
#define NV       100000
#define NE       (3 * NV)        // 300000 floats per batch row
#define NT       200000          // tets
#define NIDX     (3 * NT)        // 600000 indices
#define VOL_BLOCKS 1184

// Scratch (static device globals — no runtime allocation)
__device__ float g_xt[B * NE];              // transposed: xt[e*64 + b]
__device__ int4  g_off4[NT];                // {o0,o1,o2,pad}, o = idx*192
__device__ float g_part[VOL_BLOCKS * B];    // per-block partial |det| sums
__device__ float g_inv[B];                  // 1/cbrt(vol)
__device__ int   g_is64;                    // dtype probe result

// ---------------------------------------------------------------------------
// Kernel A: probe whether M is int64 (odd int32 words all zero) or int32.
// ---------------------------------------------------------------------------
__global__ void k_detect(const int* __restrict__ Mi) {
    int nz = 0;
    #pragma unroll
    for (int k = 0; k < 32; k++) nz |= Mi[2 * k + 1];
    g_is64 = (nz == 0) ? 1 : 0;
}

// ---------------------------------------------------------------------------
// Kernel 0: indices -> fused int4 element offsets (idx * 192 floats)
// ---------------------------------------------------------------------------
__global__ void k_prep(const void* __restrict__ Mv) {
    int t = blockIdx.x * blockDim.x + threadIdx.x;
    if (t >= NT) return;
    int i0, i1, i2;
    if (g_is64) {
        const long long* Ml = (const long long*)Mv;
        i0 = (int)Ml[3 * t]; i1 = (int)Ml[3 * t + 1]; i2 = (int)Ml[3 * t + 2];
    } else {
        const int* Mi = (const int*)Mv;
        i0 = Mi[3 * t]; i1 = Mi[3 * t + 1]; i2 = Mi[3 * t + 2];
    }
    g_off4[t] = make_int4(i0 * (3 * B), i1 * (3 * B), i2 * (3 * B), 0);
}

// ---------------------------------------------------------------------------
// Kernel 1: transpose x[b][e] -> xt[e][b]; 32e x 64b tiles, STG.128 out
// ---------------------------------------------------------------------------
__global__ void k_transpose(const float* __restrict__ x) {
    __shared__ float tile[32][65];
    const int e0 = blockIdx.x * 32;           // 9375 blocks exact
    const int tid = threadIdx.x;              // 256 threads

    #pragma unroll
    for (int k = 0; k < 8; k++) {
        int b = (tid >> 5) + k * 8;           // 0..63
        int e = tid & 31;
        tile[e][b] = x[b * NE + e0 + e];
    }
    __syncthreads();
    #pragma unroll
    for (int k = 0; k < 2; k++) {
        int e  = (tid >> 4) + k * 16;         // 0..31
        int b4 = tid & 15;                    // float4 chunk along b
        float4 v = make_float4(tile[e][4 * b4 + 0], tile[e][4 * b4 + 1],
                               tile[e][4 * b4 + 2], tile[e][4 * b4 + 3]);
        ((float4*)(g_xt + (e0 + e) * B))[b4] = v;
    }
}

// ---------------------------------------------------------------------------
// Kernel 2: per-batch |det| partial sums.
// Block = 256 threads = 32 lanes (float2 = 2 batches) x 8 tet-streams.
// Every xt load is one LDG.64, warp covers all 64 batches in one 256B request.
// One LDG.128 fetches all three fused indices.
// ---------------------------------------------------------------------------
__global__ void k_volume() {
    const int lane = threadIdx.x & 31;        // batch pair id
    const int sub  = threadIdx.x >> 5;        // tet stream 0..7

    float2 acc = make_float2(0.0f, 0.0f);
    const int stride = VOL_BLOCKS * 8;
    #pragma unroll 2
    for (int t = blockIdx.x * 8 + sub; t < NT; t += stride) {
        const int4 o = __ldg(&g_off4[t]);

        const float2* p0 = (const float2*)(g_xt + o.x) + lane;
        const float2* p1 = (const float2*)(g_xt + o.y) + lane;
        const float2* p2 = (const float2*)(g_xt + o.z) + lane;

        float2 ax = p0[0], ay = p0[32], az = p0[64];
        float2 bx = p1[0], by = p1[32], bz = p1[64];
        float2 cx = p2[0], cy = p2[32], cz = p2[64];

        float dx = ax.x * (by.x * cz.x - bz.x * cy.x)
                 - ay.x * (bx.x * cz.x - bz.x * cx.x)
                 + az.x * (bx.x * cy.x - by.x * cx.x);
        float dy = ax.y * (by.y * cz.y - bz.y * cy.y)
                 - ay.y * (bx.y * cz.y - bz.y * cx.y)
                 + az.y * (bx.y * cy.y - by.y * cx.y);
        acc.x += fabsf(dx);
        acc.y += fabsf(dy);
    }

    __shared__ float2 sred[8][32];
    sred[sub][lane] = acc;
    __syncthreads();
    if (sub == 0) {
        float2 s = acc;
        #pragma unroll
        for (int r = 1; r < 8; r++) {
            s.x += sred[r][lane].x;
            s.y += sred[r][lane].y;
        }
        g_part[blockIdx.x * B + 2 * lane + 0] = s.x;
        g_part[blockIdx.x * B + 2 * lane + 1] = s.y;
    }
}

// ---------------------------------------------------------------------------
// Kernel 3: deterministic reduce of partials + inverse cube root.
// ---------------------------------------------------------------------------
__global__ void k_reduce() {
    const int tid = threadIdx.x;
    const int b   = tid & 63;
    const int sub = tid >> 6;

    float s = 0.0f;
    for (int r = sub; r < VOL_BLOCKS; r += 4)
        s += g_part[r * B + b];

    __shared__ float sred[4][64];
    sred[sub][b] = s;
    __syncthreads();
    if (sub == 0) {
        float vol = (sred[0][b] + sred[1][b] + sred[2][b] + sred[3][b])
                    * (1.0f / 6.0f);
        g_inv[b] = 1.0f / cbrtf(vol);
    }
}

// ---------------------------------------------------------------------------
// Kernel 4: out = x * inv_scale[b], float4 streaming
// ---------------------------------------------------------------------------
__global__ void k_scale(const float* __restrict__ x, float* __restrict__ out) {
    const int bb = blockIdx.y;
    const int j4 = blockIdx.x * blockDim.x + threadIdx.x;
    const int n4 = NE / 4;                    // 75000
    if (j4 < n4) {
        float s = __ldg(&g_inv[bb]);
        const float4* xi = (const float4*)(x + bb * NE);
        float4*       oo = (float4*)(out + bb * NE);
        float4 v = xi[j4];
        v.x *= s; v.y *= s; v.z *= s; v.w *= s;
        oo[j4] = v;
    }
}

// ---------------------------------------------------------------------------
extern "C" void kernel_launch(void* const* d_in, const int* in_sizes, int n_in,
                              void* d_out, int out_size) {
    const float* x = (const float*)d_in[0];
    const void*  M = d_in[1];
    float*     out = (float*)d_out;

    k_detect<<<1, 1>>>((const int*)M);
    k_prep<<<(NT + 255) / 256, 256>>>(M);
    k_transpose<<<NE / 32, 256>>>(x);
    k_volume<<<VOL_BLOCKS, 256>>>();
    k_reduce<<<1, 256>>>();
    dim3 g((NE / 4 + 255) / 256, B);
    k_scale<<<g, 256>>>(x, out);
}

// round 4
// speedup vs baseline: 1.5957x; 1.2497x over previous
#include <cuda_runtime.h>
#include <cuda_fp16.h>

#define B        64
#define NV       100000
#define NE       (3 * NV)        // 300000 floats per batch row
#define NT       200000          // tets
#define VOL_BLOCKS 1184

// Scratch (static device globals — no runtime allocation)
__device__ __half g_xt[B * NE];             // transposed fp16: xt[e*64 + b]
__device__ int4   g_off4[NT];               // {o0,o1,o2,pad}, o = idx*192
__device__ float  g_part[VOL_BLOCKS * B];   // per-block partial |det| sums
__device__ float  g_inv[B];                 // 1/cbrt(vol)
__device__ int    g_is64;                   // dtype probe result

// ---------------------------------------------------------------------------
// Kernel A: probe whether M is int64 (odd int32 words all zero) or int32.
// ---------------------------------------------------------------------------
__global__ void k_detect(const int* __restrict__ Mi) {
    int nz = 0;
    #pragma unroll
    for (int k = 0; k < 32; k++) nz |= Mi[2 * k + 1];
    g_is64 = (nz == 0) ? 1 : 0;
}

// ---------------------------------------------------------------------------
// Kernel 0: indices -> fused int4 element offsets (idx*192, in half units)
// ---------------------------------------------------------------------------
__global__ void k_prep(const void* __restrict__ Mv) {
    int t = blockIdx.x * blockDim.x + threadIdx.x;
    if (t >= NT) return;
    int i0, i1, i2;
    if (g_is64) {
        const long long* Ml = (const long long*)Mv;
        i0 = (int)Ml[3 * t]; i1 = (int)Ml[3 * t + 1]; i2 = (int)Ml[3 * t + 2];
    } else {
        const int* Mi = (const int*)Mv;
        i0 = Mi[3 * t]; i1 = Mi[3 * t + 1]; i2 = Mi[3 * t + 2];
    }
    g_off4[t] = make_int4(i0 * (3 * B), i1 * (3 * B), i2 * (3 * B), 0);
}

// ---------------------------------------------------------------------------
// Kernel 1: transpose+convert x[b][e](f32) -> xt[e][b](f16)
// 32e x 64b tiles; store phase: each thread converts 8 halves -> STG.128
// ---------------------------------------------------------------------------
__global__ void k_transpose(const float* __restrict__ x) {
    __shared__ float tile[32][65];
    const int e0 = blockIdx.x * 32;           // 9375 blocks exact
    const int tid = threadIdx.x;              // 256 threads

    #pragma unroll
    for (int k = 0; k < 8; k++) {
        int b = (tid >> 5) + k * 8;           // 0..63
        int e = tid & 31;
        tile[e][b] = x[b * NE + e0 + e];
    }
    __syncthreads();
    {
        int e = tid >> 3;                     // 0..31
        int c = tid & 7;                      // 16-byte chunk along b (8 halves)
        __half2 h[4];
        #pragma unroll
        for (int j = 0; j < 4; j++)
            h[j] = __floats2half2_rn(tile[e][8 * c + 2 * j],
                                     tile[e][8 * c + 2 * j + 1]);
        ((int4*)(g_xt + (e0 + e) * B))[c] = *(int4*)h;
    }
}

// ---------------------------------------------------------------------------
// Kernel 2: per-batch |det| partial sums. fp16 gather, fp32 math.
// Block = 256 threads = 32 lanes (half2 = 2 batches) x 8 tet-streams.
// Each gather load: warp-wide LDG.32 over one contiguous 128B line.
// ---------------------------------------------------------------------------
__global__ void k_volume() {
    const int lane = threadIdx.x & 31;        // batch pair id
    const int sub  = threadIdx.x >> 5;        // tet stream 0..7

    float2 acc = make_float2(0.0f, 0.0f);
    const int stride = VOL_BLOCKS * 8;
    #pragma unroll 4
    for (int t = blockIdx.x * 8 + sub; t < NT; t += stride) {
        const int4 o = __ldg(&g_off4[t]);

        const __half2* p0 = (const __half2*)(g_xt + o.x) + lane;
        const __half2* p1 = (const __half2*)(g_xt + o.y) + lane;
        const __half2* p2 = (const __half2*)(g_xt + o.z) + lane;

        __half2 axh = p0[0], ayh = p0[32], azh = p0[64];
        __half2 bxh = p1[0], byh = p1[32], bzh = p1[64];
        __half2 cxh = p2[0], cyh = p2[32], czh = p2[64];

        float2 ax = __half22float2(axh), ay = __half22float2(ayh), az = __half22float2(azh);
        float2 bx = __half22float2(bxh), by = __half22float2(byh), bz = __half22float2(bzh);
        float2 cx = __half22float2(cxh), cy = __half22float2(cyh), cz = __half22float2(czh);

        float dx = ax.x * (by.x * cz.x - bz.x * cy.x)
                 - ay.x * (bx.x * cz.x - bz.x * cx.x)
                 + az.x * (bx.x * cy.x - by.x * cx.x);
        float dy = ax.y * (by.y * cz.y - bz.y * cy.y)
                 - ay.y * (bx.y * cz.y - bz.y * cx.y)
                 + az.y * (bx.y * cy.y - by.y * cx.y);
        acc.x += fabsf(dx);
        acc.y += fabsf(dy);
    }

    __shared__ float2 sred[8][32];
    sred[sub][lane] = acc;
    __syncthreads();
    if (sub == 0) {
        float2 s = acc;
        #pragma unroll
        for (int r = 1; r < 8; r++) {
            s.x += sred[r][lane].x;
            s.y += sred[r][lane].y;
        }
        g_part[blockIdx.x * B + 2 * lane + 0] = s.x;
        g_part[blockIdx.x * B + 2 * lane + 1] = s.y;
    }
}

// ---------------------------------------------------------------------------
// Kernel 3: deterministic reduce of partials + inverse cube root.
// ---------------------------------------------------------------------------
__global__ void k_reduce() {
    const int tid = threadIdx.x;
    const int b   = tid & 63;
    const int sub = tid >> 6;

    float s = 0.0f;
    for (int r = sub; r < VOL_BLOCKS; r += 4)
        s += g_part[r * B + b];

    __shared__ float sred[4][64];
    sred[sub][b] = s;
    __syncthreads();
    if (sub == 0) {
        float vol = (sred[0][b] + sred[1][b] + sred[2][b] + sred[3][b])
                    * (1.0f / 6.0f);
        g_inv[b] = 1.0f / cbrtf(vol);
    }
}

// ---------------------------------------------------------------------------
// Kernel 4: out = x * inv_scale[b], float4 streaming (fp32 precision kept)
// ---------------------------------------------------------------------------
__global__ void k_scale(const float* __restrict__ x, float* __restrict__ out) {
    const int bb = blockIdx.y;
    const int j4 = blockIdx.x * blockDim.x + threadIdx.x;
    const int n4 = NE / 4;                    // 75000
    if (j4 < n4) {
        float s = __ldg(&g_inv[bb]);
        const float4* xi = (const float4*)(x + bb * NE);
        float4*       oo = (float4*)(out + bb * NE);
        float4 v = xi[j4];
        v.x *= s; v.y *= s; v.z *= s; v.w *= s;
        oo[j4] = v;
    }
}

// ---------------------------------------------------------------------------
extern "C" void kernel_launch(void* const* d_in, const int* in_sizes, int n_in,
                              void* d_out, int out_size) {
    const float* x = (const float*)d_in[0];
    const void*  M = d_in[1];
    float*     out = (float*)d_out;

    k_detect<<<1, 1>>>((const int*)M);
    k_prep<<<(NT + 255) / 256, 256>>>(M);
    k_transpose<<<NE / 32, 256>>>(x);
    k_volume<<<VOL_BLOCKS, 256>>>();
    k_reduce<<<1, 256>>>();
    dim3 g((NE / 4 + 255) / 256, B);
    k_scale<<<g, 256>>>(x, out);
}

// round 5
// speedup vs baseline: 1.6744x; 1.0493x over previous
#include <cuda_runtime.h>
#include <cuda_fp16.h>

#define B        64
#define NV       100000
#define NE       (3 * NV)        // 300000 floats per batch row
#define NT       200000          // tets
#define VOL_BLOCKS 1184          // 8 blocks/SM * 148 SMs

// Scratch (static device globals — no runtime allocation)
__device__ __half    g_xt[B * NE];               // transposed fp16: xt[e*64 + b]
__device__ int4      g_off4[NT];                 // {o0,o1,o2,pad}, o = idx*192
__device__ float     g_part[B * VOL_BLOCKS];     // partials, [b][blk] transposed
__device__ float     g_inv[B];                   // 1/cbrt(vol)
__device__ unsigned  g_count = 0;                // last-block counter (self-resetting)

// ---------------------------------------------------------------------------
// Kernel 0: indices -> fused int4 element offsets (idx*192, in half units).
// Per-block inline dtype probe (int64 vs int32): odd words all zero => int64.
// ---------------------------------------------------------------------------
__global__ void k_prep(const void* __restrict__ Mv) {
    __shared__ int s_is64;
    if (threadIdx.x == 0) {
        const int* Mi = (const int*)Mv;
        int nz = 0;
        #pragma unroll
        for (int k = 0; k < 32; k++) nz |= Mi[2 * k + 1];
        s_is64 = (nz == 0);
    }
    __syncthreads();
    int t = blockIdx.x * blockDim.x + threadIdx.x;
    if (t >= NT) return;
    int i0, i1, i2;
    if (s_is64) {
        const long long* Ml = (const long long*)Mv;
        i0 = (int)Ml[3 * t]; i1 = (int)Ml[3 * t + 1]; i2 = (int)Ml[3 * t + 2];
    } else {
        const int* Mi = (const int*)Mv;
        i0 = Mi[3 * t]; i1 = Mi[3 * t + 1]; i2 = Mi[3 * t + 2];
    }
    g_off4[t] = make_int4(i0 * (3 * B), i1 * (3 * B), i2 * (3 * B), 0);
}

// ---------------------------------------------------------------------------
// Kernel 1: transpose+convert x[b][e](f32) -> xt[e][b](f16)
// 32e x 64b tiles; LDG.128 in, conflict-free STS, STG.128 fp16 out.
// ---------------------------------------------------------------------------
__global__ void k_transpose(const float* __restrict__ x) {
    __shared__ float tile[32][65];
    const int e0 = blockIdx.x * 32;           // 9375 blocks exact
    const int tid = threadIdx.x;              // 256 threads

    #pragma unroll
    for (int k = 0; k < 2; k++) {
        int task = tid + k * 256;
        int b  = task >> 3;                   // 0..63
        int c4 = task & 7;                    // float4 chunk along e
        float4 v = *(const float4*)(x + b * NE + e0 + 4 * c4);
        tile[4 * c4 + 0][b] = v.x;
        tile[4 * c4 + 1][b] = v.y;
        tile[4 * c4 + 2][b] = v.z;
        tile[4 * c4 + 3][b] = v.w;
    }
    __syncthreads();
    {
        int e = tid >> 3;                     // 0..31
        int c = tid & 7;                      // 16B chunk along b (8 halves)
        __half2 h[4];
        #pragma unroll
        for (int j = 0; j < 4; j++)
            h[j] = __floats2half2_rn(tile[e][8 * c + 2 * j],
                                     tile[e][8 * c + 2 * j + 1]);
        ((int4*)(g_xt + (e0 + e) * B))[c] = *(int4*)h;
    }
}

// ---------------------------------------------------------------------------
// Kernel 2: per-batch |det| partial sums + fused last-block reduce.
// Block = 256 threads = 32 lanes (half2 = 2 batches) x 8 tet-streams.
// det math in half2 (both batches per HFMA2), accumulation in fp32.
// ---------------------------------------------------------------------------
__global__ void k_volume() {
    const int tid  = threadIdx.x;
    const int lane = tid & 31;                // batch-pair id
    const int sub  = tid >> 5;                // tet stream 0..7

    float2 acc = make_float2(0.0f, 0.0f);
    const int stride = VOL_BLOCKS * 8;
    #pragma unroll 4
    for (int t = blockIdx.x * 8 + sub; t < NT; t += stride) {
        const int4 o = __ldg(&g_off4[t]);

        const __half2* p0 = (const __half2*)(g_xt + o.x) + lane;
        const __half2* p1 = (const __half2*)(g_xt + o.y) + lane;
        const __half2* p2 = (const __half2*)(g_xt + o.z) + lane;

        __half2 ax = p0[0], ay = p0[32], az = p0[64];
        __half2 bx = p1[0], by = p1[32], bz = p1[64];
        __half2 cx = p2[0], cy = p2[32], cz = p2[64];

        __half2 nbz = __hneg2(bz);
        __half2 m0 = __hfma2(by, cz, __hmul2(nbz, cy));   // by*cz - bz*cy
        __half2 m1 = __hfma2(bx, cz, __hmul2(nbz, cx));   // bx*cz - bz*cx
        __half2 m2 = __hfma2(bx, cy, __hmul2(__hneg2(by), cx)); // bx*cy - by*cx

        __half2 det = __hmul2(ax, m0);
        det = __hfma2(__hneg2(ay), m1, det);
        det = __hfma2(az, m2, det);
        det = __habs2(det);

        float2 f = __half22float2(det);
        acc.x += f.x;
        acc.y += f.y;
    }

    __shared__ float2 sred[8][32];
    sred[sub][lane] = acc;
    __syncthreads();
    if (sub == 0) {
        float2 s = acc;
        #pragma unroll
        for (int r = 1; r < 8; r++) {
            s.x += sred[r][lane].x;
            s.y += sred[r][lane].y;
        }
        // transposed partial layout: g_part[b * VOL_BLOCKS + blk]
        g_part[(2 * lane + 0) * VOL_BLOCKS + blockIdx.x] = s.x;
        g_part[(2 * lane + 1) * VOL_BLOCKS + blockIdx.x] = s.y;
    }

    // ---- fused deterministic reduce in the last block to finish ----
    __shared__ int s_last;
    if (tid == 0) {
        __threadfence();
        unsigned c = atomicAdd(&g_count, 1u);
        s_last = (c == VOL_BLOCKS - 1);
    }
    __syncthreads();
    if (!s_last) return;

    // 256 threads: b = tid>>2 (0..63), q = tid&3 (296-float contiguous chunk)
    {
        const int b = tid >> 2;
        const int q = tid & 3;
        const float4* p = (const float4*)(g_part + b * VOL_BLOCKS + q * 296);
        float s = 0.0f;
        #pragma unroll 4
        for (int i = 0; i < 74; i++) {
            float4 v = p[i];
            s += (v.x + v.y) + (v.z + v.w);
        }
        __shared__ float sq[64][4];
        sq[b][q] = s;
        __syncthreads();
        if (tid < 64) {
            float vol = ((sq[tid][0] + sq[tid][1]) + (sq[tid][2] + sq[tid][3]))
                        * (1.0f / 6.0f);
            g_inv[tid] = 1.0f / cbrtf(vol);
        }
        if (tid == 0) g_count = 0;            // reset for next graph replay
    }
}

// ---------------------------------------------------------------------------
// Kernel 3: out = x * inv_scale[b], float4 streaming (fp32 precision kept)
// ---------------------------------------------------------------------------
__global__ void k_scale(const float* __restrict__ x, float* __restrict__ out) {
    const int bb = blockIdx.y;
    const int j4 = blockIdx.x * blockDim.x + threadIdx.x;
    const int n4 = NE / 4;                    // 75000
    if (j4 < n4) {
        float s = __ldg(&g_inv[bb]);
        const float4* xi = (const float4*)(x + bb * NE);
        float4*       oo = (float4*)(out + bb * NE);
        float4 v = xi[j4];
        v.x *= s; v.y *= s; v.z *= s; v.w *= s;
        oo[j4] = v;
    }
}

// ---------------------------------------------------------------------------
extern "C" void kernel_launch(void* const* d_in, const int* in_sizes, int n_in,
                              void* d_out, int out_size) {
    const float* x = (const float*)d_in[0];
    const void*  M = d_in[1];
    float*     out = (float*)d_out;

    k_prep<<<(NT + 255) / 256, 256>>>(M);
    k_transpose<<<NE / 32, 256>>>(x);
    k_volume<<<VOL_BLOCKS, 256>>>();
    dim3 g((NE / 4 + 255) / 256, B);
    k_scale<<<g, 256>>>(x, out);
}

// round 7
// speedup vs baseline: 1.6785x; 1.0025x over previous
#include <cuda_runtime.h>
#include <cuda_fp16.h>

#define B        64
#define NV       100000
#define NE       (3 * NV)        // 300000 floats per batch row
#define NT       200000          // tets
#define VOL_BLOCKS 1184          // 8 blocks/SM * 148 SMs
#define T_TILES  (NE / 32)       // 9375 transpose tiles
#define P_BLOCKS ((NT + 255) / 256)  // 782 prep blocks

// Scratch (static device globals — no runtime allocation)
__device__ __half    g_xt[B * NE];               // transposed fp16: xt[e*64 + b]
__device__ int4      g_off4[NT];                 // {o0,o1,o2,pad}, o = idx*192
__device__ float     g_part[B * VOL_BLOCKS];     // partials, [b][blk] transposed
__device__ float     g_inv[B];                   // 1/cbrt(vol)
__device__ unsigned  g_count = 0;                // last-block counter (self-resetting)

// ---------------------------------------------------------------------------
// Kernel 0 (heterogeneous): blocks [0, T_TILES) transpose+convert x -> xt;
// blocks [T_TILES, T_TILES+P_BLOCKS) convert M -> fused int4 offsets.
// ---------------------------------------------------------------------------
__global__ void k_pt(const float* __restrict__ x, const void* __restrict__ Mv) {
    __shared__ float tile[32][65];
    const int tid = threadIdx.x;              // 256 threads

    if (blockIdx.x < T_TILES) {
        // ---------------- transpose path ----------------
        const int e0 = blockIdx.x * 32;
        #pragma unroll
        for (int k = 0; k < 2; k++) {
            int task = tid + k * 256;
            int b  = task >> 3;               // 0..63
            int c4 = task & 7;                // float4 chunk along e
            float4 v = *(const float4*)(x + b * NE + e0 + 4 * c4);
            tile[4 * c4 + 0][b] = v.x;
            tile[4 * c4 + 1][b] = v.y;
            tile[4 * c4 + 2][b] = v.z;
            tile[4 * c4 + 3][b] = v.w;
        }
        __syncthreads();
        int e = tid >> 3;                     // 0..31
        int c = tid & 7;                      // 16B chunk along b (8 halves)
        __half2 h[4];
        #pragma unroll
        for (int j = 0; j < 4; j++)
            h[j] = __floats2half2_rn(tile[e][8 * c + 2 * j],
                                     tile[e][8 * c + 2 * j + 1]);
        ((int4*)(g_xt + (e0 + e) * B))[c] = *(int4*)h;
    } else {
        // ---------------- index-prep path ----------------
        __shared__ int s_is64;
        if (tid == 0) {
            const int* Mi = (const int*)Mv;
            int nz = 0;
            #pragma unroll
            for (int k = 0; k < 32; k++) nz |= Mi[2 * k + 1];
            s_is64 = (nz == 0);
        }
        __syncthreads();
        int t = (blockIdx.x - T_TILES) * 256 + tid;
        if (t >= NT) return;
        int i0, i1, i2;
        if (s_is64) {
            const long long* Ml = (const long long*)Mv;
            i0 = (int)Ml[3 * t]; i1 = (int)Ml[3 * t + 1]; i2 = (int)Ml[3 * t + 2];
        } else {
            const int* Mi = (const int*)Mv;
            i0 = Mi[3 * t]; i1 = Mi[3 * t + 1]; i2 = Mi[3 * t + 2];
        }
        g_off4[t] = make_int4(i0 * (3 * B), i1 * (3 * B), i2 * (3 * B), 0);
    }
}

// ---------------------------------------------------------------------------
// Kernel 1: per-batch |det| partial sums + fused last-block reduce.
// Block = 256 threads = 32 lanes (half2 = 2 batches) x 8 tet-streams.
// det math in half2 (both batches per HFMA2), accumulation in fp32.
// ---------------------------------------------------------------------------
__global__ void k_volume() {
    const int tid  = threadIdx.x;
    const int lane = tid & 31;                // batch-pair id
    const int sub  = tid >> 5;                // tet stream 0..7

    float2 acc = make_float2(0.0f, 0.0f);
    const int stride = VOL_BLOCKS * 8;
    #pragma unroll 4
    for (int t = blockIdx.x * 8 + sub; t < NT; t += stride) {
        const int4 o = __ldg(&g_off4[t]);

        const __half2* p0 = (const __half2*)(g_xt + o.x) + lane;
        const __half2* p1 = (const __half2*)(g_xt + o.y) + lane;
        const __half2* p2 = (const __half2*)(g_xt + o.z) + lane;

        __half2 ax = p0[0], ay = p0[32], az = p0[64];
        __half2 bx = p1[0], by = p1[32], bz = p1[64];
        __half2 cx = p2[0], cy = p2[32], cz = p2[64];

        __half2 nbz = __hneg2(bz);
        __half2 m0 = __hfma2(by, cz, __hmul2(nbz, cy));         // by*cz - bz*cy
        __half2 m1 = __hfma2(bx, cz, __hmul2(nbz, cx));         // bx*cz - bz*cx
        __half2 m2 = __hfma2(bx, cy, __hmul2(__hneg2(by), cx)); // bx*cy - by*cx

        __half2 det = __hmul2(ax, m0);
        det = __hfma2(__hneg2(ay), m1, det);
        det = __hfma2(az, m2, det);
        det = __habs2(det);

        float2 f = __half22float2(det);
        acc.x += f.x;
        acc.y += f.y;
    }

    __shared__ float2 sred[8][32];
    sred[sub][lane] = acc;
    __syncthreads();
    if (sub == 0) {
        float2 s = acc;
        #pragma unroll
        for (int r = 1; r < 8; r++) {
            s.x += sred[r][lane].x;
            s.y += sred[r][lane].y;
        }
        g_part[(2 * lane + 0) * VOL_BLOCKS + blockIdx.x] = s.x;
        g_part[(2 * lane + 1) * VOL_BLOCKS + blockIdx.x] = s.y;
    }

    // ---- fused deterministic reduce in the last block to finish ----
    __shared__ int s_last;
    if (tid == 0) {
        __threadfence();
        unsigned c = atomicAdd(&g_count, 1u);
        s_last = (c == VOL_BLOCKS - 1);
    }
    __syncthreads();
    if (!s_last) return;

    {
        const int b = tid >> 2;               // 0..63
        const int q = tid & 3;                // 296-float contiguous chunk
        const float4* p = (const float4*)(g_part + b * VOL_BLOCKS + q * 296);
        float s = 0.0f;
        #pragma unroll 4
        for (int i = 0; i < 74; i++) {
            float4 v = p[i];
            s += (v.x + v.y) + (v.z + v.w);
        }
        __shared__ float sq[64][4];
        sq[b][q] = s;
        __syncthreads();
        if (tid < 64) {
            float vol = ((sq[tid][0] + sq[tid][1]) + (sq[tid][2] + sq[tid][3]))
                        * (1.0f / 6.0f);
            g_inv[tid] = 1.0f / cbrtf(vol);
        }
        if (tid == 0) g_count = 0;            // reset for next graph replay
    }
}

// ---------------------------------------------------------------------------
// Kernel 2: out = x * inv_scale[b]; per-thread strided float4 loop.
// grid = (37, 64); each thread handles ~8 float4s of one batch row.
// ---------------------------------------------------------------------------
__global__ void k_scale(const float* __restrict__ x, float* __restrict__ out) {
    const int bb = blockIdx.y;
    const int n4 = NE / 4;                    // 75000
    const float s = __ldg(&g_inv[bb]);
    const float4* xi = (const float4*)(x + bb * NE);
    float4*       oo = (float4*)(out + bb * NE);

    const int step = 37 * 256;                // 9472
    for (int j4 = blockIdx.x * 256 + threadIdx.x; j4 < n4; j4 += step) {
        float4 v = xi[j4];
        v.x *= s; v.y *= s; v.z *= s; v.w *= s;
        oo[j4] = v;
    }
}

// ---------------------------------------------------------------------------
extern "C" void kernel_launch(void* const* d_in, const int* in_sizes, int n_in,
                              void* d_out, int out_size) {
    const float* x = (const float*)d_in[0];
    const void*  M = d_in[1];
    float*     out = (float*)d_out;

    k_pt<<<T_TILES + P_BLOCKS, 256>>>(x, M);
    k_volume<<<VOL_BLOCKS, 256>>>();
    dim3 g(37, B);
    k_scale<<<g, 256>>>(x, out);
}